// round 1
// baseline (speedup 1.0000x reference)
#include <cuda_runtime.h>
#include <cuda_bf16.h>
#include <cstdint>
#include <cstddef>

// Problem constants (B=8, S=2048, D=1024, F=4096, E=8, capacity_factor=1.0)
#define T_TOK   16384
#define D_DIM   1024
#define F_DIM   4096
#define E_NUM   8
#define CAP     2048
#define CHUNK   256
#define NCHUNK  (T_TOK / CHUNK)

// ---------------- device scratch (static: no allocations allowed) ----------
__device__ int   g_eidx[T_TOK];
__device__ float g_gate[T_TOK];
__device__ int   g_counts[NCHUNK][E_NUM];
__device__ int   g_base[NCHUNK][E_NUM];
__device__ int   g_tok_of_slot[E_NUM * CAP];
__device__ float g_slot_gate[E_NUM * CAP];
__device__ float g_H[(size_t)E_NUM * CAP * F_DIM];   // 256 MB intermediate

// ---------------- router: logits -> softmax -> argmax -> gate --------------
// one warp per token; Wr (D x E = 32KB) cached in smem
__global__ void router_kernel(const float* __restrict__ x,
                              const float* __restrict__ Wr) {
    __shared__ float sWr[D_DIM * E_NUM];
    for (int i = threadIdx.x; i < D_DIM * E_NUM; i += blockDim.x)
        sWr[i] = Wr[i];
    __syncthreads();

    const int warp = threadIdx.x >> 5;
    const int lane = threadIdx.x & 31;
    const int tok  = blockIdx.x * (blockDim.x >> 5) + warp;
    const float* xr = x + (size_t)tok * D_DIM;

    float acc[E_NUM];
#pragma unroll
    for (int e = 0; e < E_NUM; e++) acc[e] = 0.f;

    for (int d = lane; d < D_DIM; d += 32) {
        float xv = xr[d];
        const float* w = &sWr[d * E_NUM];
#pragma unroll
        for (int e = 0; e < E_NUM; e++) acc[e] += xv * w[e];
    }
#pragma unroll
    for (int e = 0; e < E_NUM; e++) {
#pragma unroll
        for (int o = 16; o > 0; o >>= 1)
            acc[e] += __shfl_xor_sync(0xffffffffu, acc[e], o);
    }
    if (lane == 0) {
        int best = 0; float bm = acc[0];
#pragma unroll
        for (int e = 1; e < E_NUM; e++)
            if (acc[e] > bm) { bm = acc[e]; best = e; }   // strict > : first-max, matches jnp.argmax
        float s = 0.f;
#pragma unroll
        for (int e = 0; e < E_NUM; e++) s += __expf(acc[e] - bm);
        g_eidx[tok] = best;
        g_gate[tok] = 1.0f / s;    // softmax prob of the argmax expert
    }
}

// ---------------- per-chunk expert histogram -------------------------------
__global__ void count_kernel() {
    __shared__ int sc[E_NUM];
    if (threadIdx.x < E_NUM) sc[threadIdx.x] = 0;
    __syncthreads();
    int tok = blockIdx.x * CHUNK + threadIdx.x;
    atomicAdd(&sc[g_eidx[tok]], 1);
    __syncthreads();
    if (threadIdx.x < E_NUM)
        g_counts[blockIdx.x][threadIdx.x] = sc[threadIdx.x];
}

// ---------------- exclusive scan of chunk counts per expert ----------------
__global__ void scan_kernel() {
    int e = threadIdx.x;
    if (e < E_NUM) {
        int run = 0;
        for (int c = 0; c < NCHUNK; c++) {
            g_base[c][e] = run;
            run += g_counts[c][e];
        }
    }
}

// ---------------- reset slot tables (graph replays need this) --------------
__global__ void reset_kernel() {
    int i = blockIdx.x * blockDim.x + threadIdx.x;
    g_tok_of_slot[i] = -1;
    g_slot_gate[i]   = 0.f;
}

// ---------------- assign slots: order-preserving rank < cap ----------------
__global__ void assign_kernel() {
    __shared__ int se[CHUNK];
    int tok = blockIdx.x * CHUNK + threadIdx.x;
    int e = g_eidx[tok];
    se[threadIdx.x] = e;
    __syncthreads();
    int local = 0;
    for (int j = 0; j < threadIdx.x; j++) local += (se[j] == e);
    int rank = g_base[blockIdx.x][e] + local;
    if (rank < CAP) {
        int slot = e * CAP + rank;
        g_tok_of_slot[slot] = tok;
        g_slot_gate[slot]   = g_gate[tok];
    }
}

// ---------------- tiled fp32 GEMM, 128x128 tile, BK=8, 8x8 per thread ------
// PHASE 1:  H[e,slot,:] = relu( gather(x)[slot,:] @ W1[e] )     (K=D, N=F)
// PHASE 2:  out[tok,:]  = gate * ( H[e,slot,:] @ W2[e] )        (K=F, N=D)
template <int PHASE>
__global__ void __launch_bounds__(256, 2)
moe_gemm_kernel(const float* __restrict__ xin,
                const float* __restrict__ Wb,
                float* __restrict__ yout) {
    constexpr int K   = (PHASE == 1) ? D_DIM : F_DIM;
    constexpr int LDB = (PHASE == 1) ? F_DIM : D_DIM;

    const int e  = blockIdx.z;
    const int m0 = blockIdx.y * 128;
    const int n0 = blockIdx.x * 128;

    __shared__ float As[2][8][128];
    __shared__ float Bs[2][8][128];

    const int tid  = threadIdx.x;
    const int warp = tid >> 5;
    const int lane = tid & 31;

    // loaders
    const int arow = tid >> 1;
    const int akq  = (tid & 1) * 4;
    const float* aptr = nullptr;
    if (PHASE == 1) {
        int tok = g_tok_of_slot[e * CAP + m0 + arow];
        if (tok >= 0) aptr = xin + (size_t)tok * D_DIM + akq;
    } else {
        aptr = g_H + (size_t)(e * CAP + m0 + arow) * F_DIM + akq;
    }
    const int brow = tid >> 5;
    const int bcol = (tid & 31) * 4;
    const float* bptr = Wb + (size_t)e * K * LDB + (size_t)brow * LDB + n0 + bcol;

    // compute mapping: warp covers 32x64 region (4x2 warps), lane covers 8x8
    const int aoff = (warp >> 1) * 32 + (lane >> 3) * 8;
    const int boff = (warp & 1) * 64 + (lane & 7) * 8;

    float acc[8][8];
#pragma unroll
    for (int i = 0; i < 8; i++)
#pragma unroll
        for (int j = 0; j < 8; j++) acc[i][j] = 0.f;

    // prologue: stage 0
    float4 av = aptr ? *(const float4*)(aptr) : make_float4(0.f, 0.f, 0.f, 0.f);
    float4 bv = *(const float4*)(bptr);
    As[0][akq + 0][arow] = av.x;
    As[0][akq + 1][arow] = av.y;
    As[0][akq + 2][arow] = av.z;
    As[0][akq + 3][arow] = av.w;
    *(float4*)&Bs[0][brow][bcol] = bv;
    __syncthreads();

    int s = 0;
    for (int k0 = 8; k0 < K; k0 += 8) {
        av = aptr ? *(const float4*)(aptr + k0) : make_float4(0.f, 0.f, 0.f, 0.f);
        bv = *(const float4*)(bptr + (size_t)k0 * LDB);

#pragma unroll
        for (int k = 0; k < 8; k++) {
            float a[8], b[8];
            *(float4*)&a[0] = *(const float4*)&As[s][k][aoff];
            *(float4*)&a[4] = *(const float4*)&As[s][k][aoff + 4];
            *(float4*)&b[0] = *(const float4*)&Bs[s][k][boff];
            *(float4*)&b[4] = *(const float4*)&Bs[s][k][boff + 4];
#pragma unroll
            for (int i = 0; i < 8; i++)
#pragma unroll
                for (int j = 0; j < 8; j++)
                    acc[i][j] += a[i] * b[j];
        }
        int ns = s ^ 1;
        As[ns][akq + 0][arow] = av.x;
        As[ns][akq + 1][arow] = av.y;
        As[ns][akq + 2][arow] = av.z;
        As[ns][akq + 3][arow] = av.w;
        *(float4*)&Bs[ns][brow][bcol] = bv;
        __syncthreads();
        s = ns;
    }
    // epilogue compute on last stage
#pragma unroll
    for (int k = 0; k < 8; k++) {
        float a[8], b[8];
        *(float4*)&a[0] = *(const float4*)&As[s][k][aoff];
        *(float4*)&a[4] = *(const float4*)&As[s][k][aoff + 4];
        *(float4*)&b[0] = *(const float4*)&Bs[s][k][boff];
        *(float4*)&b[4] = *(const float4*)&Bs[s][k][boff + 4];
#pragma unroll
        for (int i = 0; i < 8; i++)
#pragma unroll
            for (int j = 0; j < 8; j++)
                acc[i][j] += a[i] * b[j];
    }

    if (PHASE == 1) {
#pragma unroll
        for (int i = 0; i < 8; i++) {
            int row = m0 + aoff + i;
            float* hrow = g_H + (size_t)(e * CAP + row) * F_DIM + n0 + boff;
            float4 v0, v1;
            v0.x = fmaxf(acc[i][0], 0.f); v0.y = fmaxf(acc[i][1], 0.f);
            v0.z = fmaxf(acc[i][2], 0.f); v0.w = fmaxf(acc[i][3], 0.f);
            v1.x = fmaxf(acc[i][4], 0.f); v1.y = fmaxf(acc[i][5], 0.f);
            v1.z = fmaxf(acc[i][6], 0.f); v1.w = fmaxf(acc[i][7], 0.f);
            *(float4*)(hrow)     = v0;
            *(float4*)(hrow + 4) = v1;
        }
    } else {
#pragma unroll
        for (int i = 0; i < 8; i++) {
            int row  = m0 + aoff + i;
            int slot = e * CAP + row;
            int tok  = g_tok_of_slot[slot];
            if (tok >= 0) {
                float g = g_slot_gate[slot];
                float* orow = yout + (size_t)tok * D_DIM + n0 + boff;
                float4 v0, v1;
                v0.x = acc[i][0] * g; v0.y = acc[i][1] * g;
                v0.z = acc[i][2] * g; v0.w = acc[i][3] * g;
                v1.x = acc[i][4] * g; v1.y = acc[i][5] * g;
                v1.z = acc[i][6] * g; v1.w = acc[i][7] * g;
                *(float4*)(orow)     = v0;
                *(float4*)(orow + 4) = v1;
            }
        }
    }
}

// ---------------- launch ---------------------------------------------------
extern "C" void kernel_launch(void* const* d_in, const int* in_sizes, int n_in,
                              void* d_out, int out_size) {
    const float* x  = (const float*)d_in[0];
    const float* Wr = (const float*)d_in[1];
    const float* W1 = (const float*)d_in[2];
    const float* W2 = (const float*)d_in[3];
    float* out = (float*)d_out;

    router_kernel<<<T_TOK / 8, 256>>>(x, Wr);
    count_kernel<<<NCHUNK, CHUNK>>>();
    scan_kernel<<<1, 32>>>();
    reset_kernel<<<(E_NUM * CAP) / 256, 256>>>();
    assign_kernel<<<NCHUNK, CHUNK>>>();

    moe_gemm_kernel<1><<<dim3(F_DIM / 128, CAP / 128, E_NUM), 256>>>(x, W1, nullptr);

    cudaMemsetAsync(d_out, 0, (size_t)out_size * sizeof(float));

    moe_gemm_kernel<2><<<dim3(D_DIM / 128, CAP / 128, E_NUM), 256>>>(x, W2, out);
}

// round 5
// speedup vs baseline: 5.3964x; 5.3964x over previous
#include <cuda_runtime.h>
#include <cuda_fp16.h>
#include <cstdint>
#include <cstddef>

// Problem constants (B=8, S=2048, D=1024, F=4096, E=8, capacity_factor=1.0)
#define T_TOK   16384
#define D_DIM   1024
#define F_DIM   4096
#define E_NUM   8
#define CAP     2048
#define CHUNK   256
#define NCHUNK  (T_TOK / CHUNK)

#define BM 128
#define BN 128
#define NTHREADS 128
#define ROWB 64              // 32 fp16 per k-tile row

// ---------------- device scratch (total ~224 MB, < proven 256 MB) ----------
__device__ int   g_eidx[T_TOK];
__device__ float g_gate[T_TOK];
__device__ int   g_counts[NCHUNK][E_NUM];
__device__ int   g_base[NCHUNK][E_NUM];
__device__ int   g_tok_of_slot[E_NUM * CAP];
__device__ float g_slot_gate[E_NUM * CAP];

__device__ __half g_x16[(size_t)T_TOK * D_DIM];               //  32 MB  A1 fp16
__device__ __half g_wt[(size_t)E_NUM * F_DIM * D_DIM];        //  64 MB  W1t, then W2t
__device__ __half g_h16[(size_t)E_NUM * CAP * F_DIM];         // 128 MB  H fp16
__device__ uint4  g_zrow[512];                                //   8 KB zero row

// ---------------- PTX helpers ----------------
__device__ __forceinline__ uint32_t smem_u32(const void* p) {
    uint32_t a;
    asm("{ .reg .u64 t; cvta.to.shared.u64 t, %1; cvt.u32.u64 %0, t; }" : "=r"(a) : "l"(p));
    return a;
}
__device__ __forceinline__ void sts128(uint32_t a, uint4 v) {
    asm volatile("st.shared.v4.b32 [%0], {%1,%2,%3,%4};"
                 :: "r"(a), "r"(v.x), "r"(v.y), "r"(v.z), "r"(v.w) : "memory");
}
__device__ __forceinline__ void ldsm4(uint32_t& r0, uint32_t& r1, uint32_t& r2, uint32_t& r3, uint32_t a) {
    asm volatile("ldmatrix.sync.aligned.m8n8.x4.shared.b16 {%0,%1,%2,%3}, [%4];"
                 : "=r"(r0), "=r"(r1), "=r"(r2), "=r"(r3) : "r"(a));
}
__device__ __forceinline__ void mma16816(float* c, const uint32_t* a, const uint32_t* b) {
    asm volatile("mma.sync.aligned.m16n8k16.row.col.f32.f16.f16.f32 "
                 "{%0,%1,%2,%3}, {%4,%5,%6,%7}, {%8,%9}, {%0,%1,%2,%3};"
                 : "+f"(c[0]), "+f"(c[1]), "+f"(c[2]), "+f"(c[3])
                 : "r"(a[0]), "r"(a[1]), "r"(a[2]), "r"(a[3]), "r"(b[0]), "r"(b[1]));
}

// ---------------- router ----------------
__global__ void router_kernel(const float* __restrict__ x,
                              const float* __restrict__ Wr) {
    __shared__ float sWr[D_DIM * E_NUM];
    for (int i = threadIdx.x; i < D_DIM * E_NUM; i += blockDim.x)
        sWr[i] = Wr[i];
    __syncthreads();

    const int warp = threadIdx.x >> 5;
    const int lane = threadIdx.x & 31;
    const int tok  = blockIdx.x * (blockDim.x >> 5) + warp;
    const float* xr = x + (size_t)tok * D_DIM;

    float acc[E_NUM];
#pragma unroll
    for (int e = 0; e < E_NUM; e++) acc[e] = 0.f;
    for (int d = lane; d < D_DIM; d += 32) {
        float xv = xr[d];
        const float* w = &sWr[d * E_NUM];
#pragma unroll
        for (int e = 0; e < E_NUM; e++) acc[e] += xv * w[e];
    }
#pragma unroll
    for (int e = 0; e < E_NUM; e++) {
#pragma unroll
        for (int o = 16; o > 0; o >>= 1)
            acc[e] += __shfl_xor_sync(0xffffffffu, acc[e], o);
    }
    if (lane == 0) {
        int best = 0; float bm = acc[0];
#pragma unroll
        for (int e = 1; e < E_NUM; e++)
            if (acc[e] > bm) { bm = acc[e]; best = e; }
        float s = 0.f;
#pragma unroll
        for (int e = 0; e < E_NUM; e++) s += __expf(acc[e] - bm);
        g_eidx[tok] = best;
        g_gate[tok] = 1.0f / s;
    }
}

__global__ void count_kernel() {
    __shared__ int sc[E_NUM];
    if (threadIdx.x < E_NUM) sc[threadIdx.x] = 0;
    __syncthreads();
    int tok = blockIdx.x * CHUNK + threadIdx.x;
    atomicAdd(&sc[g_eidx[tok]], 1);
    __syncthreads();
    if (threadIdx.x < E_NUM)
        g_counts[blockIdx.x][threadIdx.x] = sc[threadIdx.x];
}

__global__ void scan_kernel() {
    int e = threadIdx.x;
    if (e < E_NUM) {
        int run = 0;
        for (int c = 0; c < NCHUNK; c++) {
            g_base[c][e] = run;
            run += g_counts[c][e];
        }
    }
}

__global__ void reset_kernel() {
    int i = blockIdx.x * blockDim.x + threadIdx.x;
    g_tok_of_slot[i] = -1;
    g_slot_gate[i]   = 0.f;
    if (i < 512) g_zrow[i] = make_uint4(0u, 0u, 0u, 0u);
}

__global__ void assign_kernel() {
    __shared__ int se[CHUNK];
    int tok = blockIdx.x * CHUNK + threadIdx.x;
    int e = g_eidx[tok];
    se[threadIdx.x] = e;
    __syncthreads();
    int local = 0;
    for (int j = 0; j < threadIdx.x; j++) local += (se[j] == e);
    int rank = g_base[blockIdx.x][e] + local;
    if (rank < CAP) {
        int slot = e * CAP + rank;
        g_tok_of_slot[slot] = tok;
        g_slot_gate[slot]   = g_gate[tok];
    }
}

// ---------------- conversions ----------------
__global__ void convert_x_kernel(const float* __restrict__ x) {
    size_t i = (size_t)blockIdx.x * blockDim.x + threadIdx.x;   // over T*D
    g_x16[i] = __float2half_rn(x[i]);
}

// W [e][K][N] f32 (N contiguous) -> g_wt [e][N][K] fp16 (transpose + convert)
__global__ void convert_w_kernel(const float* __restrict__ W, int K, int N) {
    __shared__ float s[32][33];
    int e  = blockIdx.z;
    int k0 = blockIdx.x * 32, n0 = blockIdx.y * 32;
    const float* src = W + (size_t)e * K * N;
    __half* d = g_wt + (size_t)e * N * K;
    int tx = threadIdx.x, ty = threadIdx.y;   // (32, 8)
#pragma unroll
    for (int i = 0; i < 4; i++) {
        int kl = ty + i * 8;
        s[kl][tx] = src[(size_t)(k0 + kl) * N + n0 + tx];
    }
    __syncthreads();
#pragma unroll
    for (int i = 0; i < 4; i++) {
        int nl = ty + i * 8;
        d[(size_t)(n0 + nl) * K + k0 + tx] = __float2half_rn(s[tx][nl]);
    }
}

// ---------------- HMMA GEMM: 128x128 tile, BK=32, single-buffer LDG->STS ----
// smem swizzle: 16B granule g of row r stored at granule (g ^ ((r>>1)&3))
// PHASE 1: H = relu( gather(x16) @ W1t^T )  (K=1024)
// PHASE 2: out[tok] = gate * ( H @ W2t^T )  (K=4096)
template <int PHASE>
__global__ void __launch_bounds__(NTHREADS)
moe_mma_gemm(float* __restrict__ out) {
    constexpr int KA = (PHASE == 1) ? D_DIM : F_DIM;
    constexpr int NC = KA / 32;                 // 32 / 128 k-tiles
    constexpr int NT = (PHASE == 1) ? F_DIM : D_DIM;

    __shared__ uint4 dsm[1024];                 // 16 KB: A 8KB + B 8KB
    const uint32_t sbase = smem_u32(dsm);
    const uint32_t aS = sbase, bS = sbase + 8192;

    const int tid = threadIdx.x;
    const int e = blockIdx.z, m0 = blockIdx.y * BM, n0 = blockIdx.x * BN;

    // ---- load mapping: rbase = tid>>2 (0..31), rows rbase+32i; granule cix = tid&3
    const int rbase = tid >> 2;
    const int cix   = tid & 3;
    const uint32_t dst0 = (uint32_t)rbase * ROWB + (uint32_t)((cix ^ ((rbase >> 1) & 3)) << 4);

    const char* pA[4];
    const char* pB[4];
    uint32_t    mskA = 0;
#pragma unroll
    for (int i = 0; i < 4; i++) {
        int row = rbase + i * 32;
        if (PHASE == 1) {
            int tok = g_tok_of_slot[e * CAP + m0 + row];
            if (tok >= 0) { pA[i] = (const char*)(g_x16 + (size_t)tok * D_DIM) + cix * 16; mskA |= (1u << i); }
            else          { pA[i] = (const char*)g_zrow; }
        } else {
            pA[i] = (const char*)(g_h16 + (size_t)(e * CAP + m0 + row) * F_DIM) + cix * 16;
            mskA |= (1u << i);
        }
        pB[i] = (const char*)(g_wt + ((size_t)e * NT + n0 + row) * KA) + cix * 16;
    }

    uint4 rA[4], rB[4];
    auto ldg_tile = [&](int c) {
        uint32_t koff = (uint32_t)c * ROWB;
#pragma unroll
        for (int i = 0; i < 4; i++) {
            rA[i] = *(const uint4*)(pA[i] + (((mskA >> i) & 1) ? koff : 0u));
            rB[i] = *(const uint4*)(pB[i] + koff);
        }
    };
    auto sts_tile = [&]() {
#pragma unroll
        for (int i = 0; i < 4; i++) {
            sts128(aS + dst0 + i * 2048, rA[i]);
            sts128(bS + dst0 + i * 2048, rB[i]);
        }
    };

    // ---- compute mapping: 4 warps 2x2, warp tile 64x64
    const int w = tid >> 5, l = tid & 31;
    const int warp_m = (w & 1) * 64, warp_n = (w >> 1) * 64;
    const int a_ml = warp_m + (l & 15);
    const int a_ks = (l >> 4);
    const int b_nl = warp_n + (l & 7) + ((l & 16) >> 1);
    const int b_ks = (l >> 3) & 1;
    const int fa = (a_ml >> 1) & 3, fb = (b_nl >> 1) & 3;

    float acc[4][8][4];
#pragma unroll
    for (int i = 0; i < 4; i++)
#pragma unroll
        for (int j = 0; j < 8; j++)
#pragma unroll
            for (int q = 0; q < 4; q++) acc[i][j][q] = 0.f;

    ldg_tile(0);

    for (int c = 0; c < NC; c++) {
        sts_tile();
        __syncthreads();
        if (c + 1 < NC) ldg_tile(c + 1);     // hidden under compute

#pragma unroll
        for (int ks = 0; ks < 2; ks++) {
            uint32_t af[4][4], bf[4][4];
#pragma unroll
            for (int mf = 0; mf < 4; mf++) {
                uint32_t addr = aS + (uint32_t)(a_ml + mf * 16) * ROWB
                              + (uint32_t)(((ks * 2 + a_ks) ^ fa) << 4);
                ldsm4(af[mf][0], af[mf][1], af[mf][2], af[mf][3], addr);
            }
#pragma unroll
            for (int g = 0; g < 4; g++) {
                uint32_t addr = bS + (uint32_t)(b_nl + g * 16) * ROWB
                              + (uint32_t)(((ks * 2 + b_ks) ^ fb) << 4);
                ldsm4(bf[g][0], bf[g][1], bf[g][2], bf[g][3], addr);
            }
#pragma unroll
            for (int mf = 0; mf < 4; mf++)
#pragma unroll
                for (int nf = 0; nf < 8; nf++)
                    mma16816(acc[mf][nf], af[mf], &bf[nf >> 1][(nf & 1) * 2]);
        }
        __syncthreads();
    }

    // ---- epilogue ----
    const int gid = l >> 2, tg = l & 3;
    if (PHASE == 1) {
#pragma unroll
        for (int mf = 0; mf < 4; mf++) {
#pragma unroll
            for (int half = 0; half < 2; half++) {
                int row = warp_m + mf * 16 + gid + half * 8;
                int slot = e * CAP + m0 + row;
                __half* hrow = g_h16 + (size_t)slot * F_DIM;
#pragma unroll
                for (int nf = 0; nf < 8; nf++) {
                    int col = n0 + warp_n + nf * 8 + tg * 2;
                    float v0 = fmaxf(acc[mf][nf][half * 2 + 0], 0.f);
                    float v1 = fmaxf(acc[mf][nf][half * 2 + 1], 0.f);
                    *(__half2*)(hrow + col) = __halves2half2(__float2half_rn(v0), __float2half_rn(v1));
                }
            }
        }
    } else {
#pragma unroll
        for (int mf = 0; mf < 4; mf++) {
#pragma unroll
            for (int half = 0; half < 2; half++) {
                int row = warp_m + mf * 16 + gid + half * 8;
                int slot = e * CAP + m0 + row;
                int tok = g_tok_of_slot[slot];
                if (tok < 0) continue;
                float g = g_slot_gate[slot];
                float* orow = out + (size_t)tok * D_DIM;
#pragma unroll
                for (int nf = 0; nf < 8; nf++) {
                    int col = n0 + warp_n + nf * 8 + tg * 2;
                    float2 v;
                    v.x = acc[mf][nf][half * 2 + 0] * g;
                    v.y = acc[mf][nf][half * 2 + 1] * g;
                    *(float2*)(orow + col) = v;
                }
            }
        }
    }
}

// ---------------- launch ----------------
extern "C" void kernel_launch(void* const* d_in, const int* in_sizes, int n_in,
                              void* d_out, int out_size) {
    const float* x  = (const float*)d_in[0];
    const float* Wr = (const float*)d_in[1];
    const float* W1 = (const float*)d_in[2];
    const float* W2 = (const float*)d_in[3];
    float* out = (float*)d_out;

    convert_x_kernel<<<(T_TOK * D_DIM) / 256, 256>>>(x);

    // routing chain
    router_kernel<<<T_TOK / 8, 256>>>(x, Wr);
    count_kernel<<<NCHUNK, CHUNK>>>();
    scan_kernel<<<1, 32>>>();
    reset_kernel<<<(E_NUM * CAP) / 256, 256>>>();
    assign_kernel<<<NCHUNK, CHUNK>>>();

    // W1^T -> shared union buffer, then GEMM1
    convert_w_kernel<<<dim3(D_DIM / 32, F_DIM / 32, E_NUM), dim3(32, 8)>>>(W1, D_DIM, F_DIM);
    moe_mma_gemm<1><<<dim3(F_DIM / BN, CAP / BM, E_NUM), NTHREADS>>>(nullptr);

    // W2^T overwrites union buffer (stream-ordered after GEMM1), then GEMM2
    convert_w_kernel<<<dim3(F_DIM / 32, D_DIM / 32, E_NUM), dim3(32, 8)>>>(W2, F_DIM, D_DIM);

    cudaMemsetAsync(d_out, 0, (size_t)out_size * sizeof(float));

    moe_mma_gemm<2><<<dim3(D_DIM / BN, CAP / BM, E_NUM), NTHREADS>>>(out);
}

// round 6
// speedup vs baseline: 5.9314x; 1.0991x over previous
#include <cuda_runtime.h>
#include <cuda_fp16.h>
#include <cstdint>
#include <cstddef>

// Problem constants (B=8, S=2048, D=1024, F=4096, E=8, capacity_factor=1.0)
#define T_TOK   16384
#define D_DIM   1024
#define F_DIM   4096
#define E_NUM   8
#define CAP     2048
#define CHUNK   256
#define NCHUNK  (T_TOK / CHUNK)

#define BM 128
#define BN 128
#define NTHREADS 128
#define ROWB 64              // 32 fp16 per k-tile row
#define STAGE_B 16384        // A 8KB + B 8KB per stage

// ---------------- device scratch (total ~224 MB, proven-safe size) ---------
__device__ int   g_eidx[T_TOK];
__device__ float g_gate[T_TOK];
__device__ int   g_counts[NCHUNK][E_NUM];
__device__ int   g_base[NCHUNK][E_NUM];
__device__ int   g_tok_of_slot[E_NUM * CAP];
__device__ float g_slot_gate[E_NUM * CAP];

__device__ __half g_x16[(size_t)T_TOK * D_DIM];               //  32 MB  A1 fp16
__device__ __half g_wt[(size_t)E_NUM * F_DIM * D_DIM];        //  64 MB  W1t, then W2t
__device__ __half g_h16[(size_t)E_NUM * CAP * F_DIM];         // 128 MB  H fp16
__device__ uint4  g_zrow[512];                                //   8 KB zero row

// ---------------- PTX helpers ----------------
__device__ __forceinline__ uint32_t smem_u32(const void* p) {
    uint32_t a;
    asm("{ .reg .u64 t; cvta.to.shared.u64 t, %1; cvt.u32.u64 %0, t; }" : "=r"(a) : "l"(p));
    return a;
}
__device__ __forceinline__ void sts128(uint32_t a, uint4 v) {
    asm volatile("st.shared.v4.b32 [%0], {%1,%2,%3,%4};"
                 :: "r"(a), "r"(v.x), "r"(v.y), "r"(v.z), "r"(v.w) : "memory");
}
__device__ __forceinline__ void ldsm4(uint32_t& r0, uint32_t& r1, uint32_t& r2, uint32_t& r3, uint32_t a) {
    asm volatile("ldmatrix.sync.aligned.m8n8.x4.shared.b16 {%0,%1,%2,%3}, [%4];"
                 : "=r"(r0), "=r"(r1), "=r"(r2), "=r"(r3) : "r"(a));
}
__device__ __forceinline__ void mma16816(float* c, const uint32_t* a, const uint32_t* b) {
    asm volatile("mma.sync.aligned.m16n8k16.row.col.f32.f16.f16.f32 "
                 "{%0,%1,%2,%3}, {%4,%5,%6,%7}, {%8,%9}, {%0,%1,%2,%3};"
                 : "+f"(c[0]), "+f"(c[1]), "+f"(c[2]), "+f"(c[3])
                 : "r"(a[0]), "r"(a[1]), "r"(a[2]), "r"(a[3]), "r"(b[0]), "r"(b[1]));
}

// ---------------- router (+ fused x -> fp16 conversion) ----------------
__global__ void router_kernel(const float* __restrict__ x,
                              const float* __restrict__ Wr) {
    __shared__ float sWr[D_DIM * E_NUM];
    for (int i = threadIdx.x; i < D_DIM * E_NUM; i += blockDim.x)
        sWr[i] = Wr[i];
    __syncthreads();

    const int warp = threadIdx.x >> 5;
    const int lane = threadIdx.x & 31;
    const int tok  = blockIdx.x * (blockDim.x >> 5) + warp;
    const float* xr = x + (size_t)tok * D_DIM;
    __half* xo = g_x16 + (size_t)tok * D_DIM;

    float acc[E_NUM];
#pragma unroll
    for (int e = 0; e < E_NUM; e++) acc[e] = 0.f;
    for (int d = lane; d < D_DIM; d += 32) {
        float xv = xr[d];
        xo[d] = __float2half_rn(xv);               // fused conversion
        const float* w = &sWr[d * E_NUM];
#pragma unroll
        for (int e = 0; e < E_NUM; e++) acc[e] += xv * w[e];
    }
#pragma unroll
    for (int e = 0; e < E_NUM; e++) {
#pragma unroll
        for (int o = 16; o > 0; o >>= 1)
            acc[e] += __shfl_xor_sync(0xffffffffu, acc[e], o);
    }
    if (lane == 0) {
        int best = 0; float bm = acc[0];
#pragma unroll
        for (int e = 1; e < E_NUM; e++)
            if (acc[e] > bm) { bm = acc[e]; best = e; }
        float s = 0.f;
#pragma unroll
        for (int e = 0; e < E_NUM; e++) s += __expf(acc[e] - bm);
        g_eidx[tok] = best;
        g_gate[tok] = 1.0f / s;
    }
}

__global__ void count_kernel() {
    __shared__ int sc[E_NUM];
    if (threadIdx.x < E_NUM) sc[threadIdx.x] = 0;
    __syncthreads();
    int tok = blockIdx.x * CHUNK + threadIdx.x;
    atomicAdd(&sc[g_eidx[tok]], 1);
    __syncthreads();
    if (threadIdx.x < E_NUM)
        g_counts[blockIdx.x][threadIdx.x] = sc[threadIdx.x];
}

// warp-parallel scan: warp w = expert w, lanes cover 64 chunks (2 each)
__global__ void scan_kernel() {
    int w = threadIdx.x >> 5, lane = threadIdx.x & 31;
    int c0 = g_counts[2 * lane][w];
    int c1 = g_counts[2 * lane + 1][w];
    int s = c0 + c1;
    int pre = s;
#pragma unroll
    for (int o = 1; o < 32; o <<= 1) {
        int t = __shfl_up_sync(0xffffffffu, pre, o);
        if (lane >= o) pre += t;
    }
    int excl = pre - s;
    g_base[2 * lane][w]     = excl;
    g_base[2 * lane + 1][w] = excl + c0;
}

__global__ void reset_kernel() {
    int i = blockIdx.x * blockDim.x + threadIdx.x;
    g_tok_of_slot[i] = -1;
    g_slot_gate[i]   = 0.f;
    if (i < 512) g_zrow[i] = make_uint4(0u, 0u, 0u, 0u);
}

__global__ void assign_kernel() {
    __shared__ int se[CHUNK];
    int tok = blockIdx.x * CHUNK + threadIdx.x;
    int e = g_eidx[tok];
    se[threadIdx.x] = e;
    __syncthreads();
    int local = 0;
    for (int j = 0; j < threadIdx.x; j++) local += (se[j] == e);
    int rank = g_base[blockIdx.x][e] + local;
    if (rank < CAP) {
        int slot = e * CAP + rank;
        g_tok_of_slot[slot] = tok;
        g_slot_gate[slot]   = g_gate[tok];
    }
}

// W [e][K][N] f32 (N contiguous) -> g_wt [e][N][K] fp16 (transpose + convert)
__global__ void convert_w_kernel(const float* __restrict__ W, int K, int N) {
    __shared__ float s[32][33];
    int e  = blockIdx.z;
    int k0 = blockIdx.x * 32, n0 = blockIdx.y * 32;
    const float* src = W + (size_t)e * K * N;
    __half* d = g_wt + (size_t)e * N * K;
    int tx = threadIdx.x, ty = threadIdx.y;   // (32, 8)
#pragma unroll
    for (int i = 0; i < 4; i++) {
        int kl = ty + i * 8;
        s[kl][tx] = src[(size_t)(k0 + kl) * N + n0 + tx];
    }
    __syncthreads();
#pragma unroll
    for (int i = 0; i < 4; i++) {
        int nl = ty + i * 8;
        d[(size_t)(n0 + nl) * K + k0 + tx] = __float2half_rn(s[tx][nl]);
    }
}

// ---------------- HMMA GEMM: 128x128 tile, BK=32, double-buffered smem -----
// smem swizzle: 16B granule g of row r stored at granule (g ^ ((r>>1)&3))
// PHASE 1: H = relu( gather(x16) @ W1t^T )  (K=1024)
// PHASE 2: out[tok] = gate * ( H @ W2t^T )  (K=4096)
template <int PHASE>
__global__ void __launch_bounds__(NTHREADS, 2)
moe_mma_gemm(float* __restrict__ out) {
    constexpr int KA = (PHASE == 1) ? D_DIM : F_DIM;
    constexpr int NC = KA / 32;                 // 32 / 128 k-tiles
    constexpr int NT = (PHASE == 1) ? F_DIM : D_DIM;

    __shared__ uint4 dsm[2048];                 // 32 KB: 2 stages x (A 8KB + B 8KB)
    const uint32_t sbase = smem_u32(dsm);

    const int tid = threadIdx.x;
    const int e = blockIdx.z, m0 = blockIdx.y * BM, n0 = blockIdx.x * BN;

    // ---- load mapping: rbase = tid>>2 (0..31), rows rbase+32i; granule cix = tid&3
    const int rbase = tid >> 2;
    const int cix   = tid & 3;
    const uint32_t dst0 = (uint32_t)rbase * ROWB + (uint32_t)((cix ^ ((rbase >> 1) & 3)) << 4);

    const char* pA[4];
    const char* pB[4];
    uint32_t    mskA = 0;
#pragma unroll
    for (int i = 0; i < 4; i++) {
        int row = rbase + i * 32;
        if (PHASE == 1) {
            int tok = g_tok_of_slot[e * CAP + m0 + row];
            if (tok >= 0) { pA[i] = (const char*)(g_x16 + (size_t)tok * D_DIM) + cix * 16; mskA |= (1u << i); }
            else          { pA[i] = (const char*)g_zrow; }
        } else {
            pA[i] = (const char*)(g_h16 + (size_t)(e * CAP + m0 + row) * F_DIM) + cix * 16;
            mskA |= (1u << i);
        }
        pB[i] = (const char*)(g_wt + ((size_t)e * NT + n0 + row) * KA) + cix * 16;
    }

    uint4 rA[4], rB[4];
    auto ldg_tile = [&](int c) {
        uint32_t koff = (uint32_t)c * ROWB;
#pragma unroll
        for (int i = 0; i < 4; i++) {
            rA[i] = *(const uint4*)(pA[i] + (((mskA >> i) & 1) ? koff : 0u));
            rB[i] = *(const uint4*)(pB[i] + koff);
        }
    };
    auto sts_tile = [&](int buf) {
        uint32_t aS = sbase + (uint32_t)buf * STAGE_B;
        uint32_t bS = aS + 8192;
#pragma unroll
        for (int i = 0; i < 4; i++) {
            sts128(aS + dst0 + i * 2048, rA[i]);
            sts128(bS + dst0 + i * 2048, rB[i]);
        }
    };

    // ---- compute mapping: 4 warps 2x2, warp tile 64x64
    const int w = tid >> 5, l = tid & 31;
    const int warp_m = (w & 1) * 64, warp_n = (w >> 1) * 64;
    const int a_ml = warp_m + (l & 15);
    const int a_ks = (l >> 4);
    const int b_nl = warp_n + (l & 7) + ((l & 16) >> 1);
    const int b_ks = (l >> 3) & 1;
    const int fa = (a_ml >> 1) & 3, fb = (b_nl >> 1) & 3;

    float acc[4][8][4];
#pragma unroll
    for (int i = 0; i < 4; i++)
#pragma unroll
        for (int j = 0; j < 8; j++)
#pragma unroll
            for (int q = 0; q < 4; q++) acc[i][j][q] = 0.f;

    ldg_tile(0);
    sts_tile(0);
    __syncthreads();

    for (int c = 0; c < NC; c++) {
        if (c + 1 < NC) ldg_tile(c + 1);        // prefetch; hidden under compute

        uint32_t aS = sbase + (uint32_t)(c & 1) * STAGE_B;
        uint32_t bS = aS + 8192;
#pragma unroll
        for (int ks = 0; ks < 2; ks++) {
            uint32_t af[4][4], bf[4][4];
#pragma unroll
            for (int mf = 0; mf < 4; mf++) {
                uint32_t addr = aS + (uint32_t)(a_ml + mf * 16) * ROWB
                              + (uint32_t)(((ks * 2 + a_ks) ^ fa) << 4);
                ldsm4(af[mf][0], af[mf][1], af[mf][2], af[mf][3], addr);
            }
#pragma unroll
            for (int g = 0; g < 4; g++) {
                uint32_t addr = bS + (uint32_t)(b_nl + g * 16) * ROWB
                              + (uint32_t)(((ks * 2 + b_ks) ^ fb) << 4);
                ldsm4(bf[g][0], bf[g][1], bf[g][2], bf[g][3], addr);
            }
#pragma unroll
            for (int mf = 0; mf < 4; mf++)
#pragma unroll
                for (int nf = 0; nf < 8; nf++)
                    mma16816(acc[mf][nf], af[mf], &bf[nf >> 1][(nf & 1) * 2]);
        }

        if (c + 1 < NC) {
            sts_tile((c + 1) & 1);              // write alternate buffer
            __syncthreads();                    // single barrier per k-tile
        }
    }

    // ---- epilogue ----
    const int gid = l >> 2, tg = l & 3;
    if (PHASE == 1) {
#pragma unroll
        for (int mf = 0; mf < 4; mf++) {
#pragma unroll
            for (int half = 0; half < 2; half++) {
                int row = warp_m + mf * 16 + gid + half * 8;
                int slot = e * CAP + m0 + row;
                __half* hrow = g_h16 + (size_t)slot * F_DIM;
#pragma unroll
                for (int nf = 0; nf < 8; nf++) {
                    int col = n0 + warp_n + nf * 8 + tg * 2;
                    float v0 = fmaxf(acc[mf][nf][half * 2 + 0], 0.f);
                    float v1 = fmaxf(acc[mf][nf][half * 2 + 1], 0.f);
                    *(__half2*)(hrow + col) = __halves2half2(__float2half_rn(v0), __float2half_rn(v1));
                }
            }
        }
    } else {
#pragma unroll
        for (int mf = 0; mf < 4; mf++) {
#pragma unroll
            for (int half = 0; half < 2; half++) {
                int row = warp_m + mf * 16 + gid + half * 8;
                int slot = e * CAP + m0 + row;
                int tok = g_tok_of_slot[slot];
                if (tok < 0) continue;
                float g = g_slot_gate[slot];
                float* orow = out + (size_t)tok * D_DIM;
#pragma unroll
                for (int nf = 0; nf < 8; nf++) {
                    int col = n0 + warp_n + nf * 8 + tg * 2;
                    float2 v;
                    v.x = acc[mf][nf][half * 2 + 0] * g;
                    v.y = acc[mf][nf][half * 2 + 1] * g;
                    *(float2*)(orow + col) = v;
                }
            }
        }
    }
}

// ---------------- launch ----------------
extern "C" void kernel_launch(void* const* d_in, const int* in_sizes, int n_in,
                              void* d_out, int out_size) {
    const float* x  = (const float*)d_in[0];
    const float* Wr = (const float*)d_in[1];
    const float* W1 = (const float*)d_in[2];
    const float* W2 = (const float*)d_in[3];
    float* out = (float*)d_out;

    // routing chain (router also emits x as fp16)
    router_kernel<<<T_TOK / 8, 256>>>(x, Wr);
    count_kernel<<<NCHUNK, CHUNK>>>();
    scan_kernel<<<1, 256>>>();
    reset_kernel<<<(E_NUM * CAP) / 256, 256>>>();
    assign_kernel<<<NCHUNK, CHUNK>>>();

    // W1^T -> union buffer, then GEMM1
    convert_w_kernel<<<dim3(D_DIM / 32, F_DIM / 32, E_NUM), dim3(32, 8)>>>(W1, D_DIM, F_DIM);
    moe_mma_gemm<1><<<dim3(F_DIM / BN, CAP / BM, E_NUM), NTHREADS>>>(nullptr);

    // W2^T overwrites union buffer (stream-ordered after GEMM1), then GEMM2
    convert_w_kernel<<<dim3(F_DIM / 32, D_DIM / 32, E_NUM), dim3(32, 8)>>>(W2, F_DIM, D_DIM);

    cudaMemsetAsync(d_out, 0, (size_t)out_size * sizeof(float));

    moe_mma_gemm<2><<<dim3(D_DIM / BN, CAP / BM, E_NUM), NTHREADS>>>(out);
}

// round 7
// speedup vs baseline: 5.9347x; 1.0006x over previous
#include <cuda_runtime.h>
#include <cuda_fp16.h>
#include <cstdint>
#include <cstddef>

// Problem constants (B=8, S=2048, D=1024, F=4096, E=8, capacity_factor=1.0)
#define T_TOK   16384
#define D_DIM   1024
#define F_DIM   4096
#define E_NUM   8
#define CAP     2048
#define CHUNK   256
#define NCHUNK  (T_TOK / CHUNK)

#define BM 128
#define BN 128
#define NTHREADS 128
#define ROWB 64              // 32 fp16 per k-tile row
#define STAGE_B 16384        // A 8KB + B 8KB per stage (3 stages = 48KB)

// ---------------- device scratch (total ~224 MB, proven-safe size) ---------
__device__ int   g_eidx[T_TOK];
__device__ float g_gate[T_TOK];
__device__ int   g_counts[NCHUNK][E_NUM];     // zero-init; scan re-zeroes after read
__device__ int   g_base[NCHUNK][E_NUM];
__device__ int   g_tok_of_slot[E_NUM * CAP];
__device__ float g_slot_gate[E_NUM * CAP];

__device__ __half g_x16[(size_t)T_TOK * D_DIM];               //  32 MB  A1 fp16
__device__ __half g_wt[(size_t)E_NUM * F_DIM * D_DIM];        //  64 MB  W1t, then W2t
__device__ __half g_h16[(size_t)E_NUM * CAP * F_DIM];         // 128 MB  H fp16
__device__ uint4  g_zrow[512];                                //   8 KB zero row

// ---------------- PTX helpers ----------------
__device__ __forceinline__ uint32_t smem_u32(const void* p) {
    uint32_t a;
    asm("{ .reg .u64 t; cvta.to.shared.u64 t, %1; cvt.u32.u64 %0, t; }" : "=r"(a) : "l"(p));
    return a;
}
__device__ __forceinline__ void sts128(uint32_t a, uint4 v) {
    asm volatile("st.shared.v4.b32 [%0], {%1,%2,%3,%4};"
                 :: "r"(a), "r"(v.x), "r"(v.y), "r"(v.z), "r"(v.w) : "memory");
}
__device__ __forceinline__ void ldsm4(uint32_t& r0, uint32_t& r1, uint32_t& r2, uint32_t& r3, uint32_t a) {
    asm volatile("ldmatrix.sync.aligned.m8n8.x4.shared.b16 {%0,%1,%2,%3}, [%4];"
                 : "=r"(r0), "=r"(r1), "=r"(r2), "=r"(r3) : "r"(a));
}
__device__ __forceinline__ void mma16816(float* c, const uint32_t* a, const uint32_t* b) {
    asm volatile("mma.sync.aligned.m16n8k16.row.col.f32.f16.f16.f32 "
                 "{%0,%1,%2,%3}, {%4,%5,%6,%7}, {%8,%9}, {%0,%1,%2,%3};"
                 : "+f"(c[0]), "+f"(c[1]), "+f"(c[2]), "+f"(c[3])
                 : "r"(a[0]), "r"(a[1]), "r"(a[2]), "r"(a[3]), "r"(b[0]), "r"(b[1]));
}

// ---------------- router (+ fused x->fp16 + fused chunk histogram) --------
__global__ void router_kernel(const float* __restrict__ x,
                              const float* __restrict__ Wr) {
    __shared__ float sWr[D_DIM * E_NUM];
    for (int i = threadIdx.x; i < D_DIM * E_NUM; i += blockDim.x)
        sWr[i] = Wr[i];
    __syncthreads();

    const int warp = threadIdx.x >> 5;
    const int lane = threadIdx.x & 31;
    const int tok  = blockIdx.x * (blockDim.x >> 5) + warp;
    const float* xr = x + (size_t)tok * D_DIM;
    __half* xo = g_x16 + (size_t)tok * D_DIM;

    float acc[E_NUM];
#pragma unroll
    for (int e = 0; e < E_NUM; e++) acc[e] = 0.f;
    for (int d = lane; d < D_DIM; d += 32) {
        float xv = xr[d];
        xo[d] = __float2half_rn(xv);               // fused conversion
        const float* w = &sWr[d * E_NUM];
#pragma unroll
        for (int e = 0; e < E_NUM; e++) acc[e] += xv * w[e];
    }
#pragma unroll
    for (int e = 0; e < E_NUM; e++) {
#pragma unroll
        for (int o = 16; o > 0; o >>= 1)
            acc[e] += __shfl_xor_sync(0xffffffffu, acc[e], o);
    }
    if (lane == 0) {
        int best = 0; float bm = acc[0];
#pragma unroll
        for (int e = 1; e < E_NUM; e++)
            if (acc[e] > bm) { bm = acc[e]; best = e; }
        float s = 0.f;
#pragma unroll
        for (int e = 0; e < E_NUM; e++) s += __expf(acc[e] - bm);
        g_eidx[tok] = best;
        g_gate[tok] = 1.0f / s;
        atomicAdd(&g_counts[tok >> 8][best], 1);   // fused chunk histogram
    }
}

// ---------------- W tile transpose+convert (device body) -------------------
__device__ __forceinline__ void convert_w_tile(const float* __restrict__ W,
                                               int K, int N, int e, int k0, int n0,
                                               int tx, int ty) {
    __shared__ float s[32][33];
    const float* src = W + (size_t)e * K * N;
    __half* d = g_wt + (size_t)e * N * K;
#pragma unroll
    for (int i = 0; i < 4; i++) {
        int kl = ty + i * 8;
        s[kl][tx] = src[(size_t)(k0 + kl) * N + n0 + tx];
    }
    __syncthreads();
#pragma unroll
    for (int i = 0; i < 4; i++) {
        int nl = ty + i * 8;
        d[(size_t)(n0 + nl) * K + k0 + tx] = __float2half_rn(s[tx][nl]);
    }
}

// ---------------- fused: reset (b<64) | scan (b==64) | convert W1 (b>=65) --
__global__ void fused_setup_kernel(const float* __restrict__ W1) {
    int b = blockIdx.x;
    int tid = threadIdx.x;
    if (b < 64) {
        int i = b * 256 + tid;
        g_tok_of_slot[i] = -1;
        g_slot_gate[i]   = 0.f;
        if (i < 512) g_zrow[i] = make_uint4(0u, 0u, 0u, 0u);
    } else if (b == 64) {
        // warp w = expert w; lanes cover 64 chunks (2 each); re-zero counts after read
        int w = tid >> 5, lane = tid & 31;
        int c0 = g_counts[2 * lane][w];
        int c1 = g_counts[2 * lane + 1][w];
        g_counts[2 * lane][w] = 0;                 // ready for next graph replay
        g_counts[2 * lane + 1][w] = 0;
        int s = c0 + c1;
        int pre = s;
#pragma unroll
        for (int o = 1; o < 32; o <<= 1) {
            int t = __shfl_up_sync(0xffffffffu, pre, o);
            if (lane >= o) pre += t;
        }
        int excl = pre - s;
        g_base[2 * lane][w]     = excl;
        g_base[2 * lane + 1][w] = excl + c0;
    } else {
        // convert W1 [e][D][F] -> g_wt [e][F][D]; tiles: kt in [0,32), nt in [0,128), e in [0,8)
        int idx = b - 65;
        int kt = idx & 31;
        int nt = (idx >> 5) & 127;
        int e  = idx >> 12;
        convert_w_tile(W1, D_DIM, F_DIM, e, kt * 32, nt * 32, tid & 31, tid >> 5);
    }
}

__global__ void assign_kernel() {
    __shared__ int se[CHUNK];
    int tok = blockIdx.x * CHUNK + threadIdx.x;
    int e = g_eidx[tok];
    se[threadIdx.x] = e;
    __syncthreads();
    int local = 0;
    for (int j = 0; j < threadIdx.x; j++) local += (se[j] == e);
    int rank = g_base[blockIdx.x][e] + local;
    if (rank < CAP) {
        int slot = e * CAP + rank;
        g_tok_of_slot[slot] = tok;
        g_slot_gate[slot]   = g_gate[tok];
    }
}

// W2 [e][F][D] -> g_wt [e][D][F]
__global__ void convert_w2_kernel(const float* __restrict__ W2) {
    convert_w_tile(W2, F_DIM, D_DIM, blockIdx.z, blockIdx.x * 32, blockIdx.y * 32,
                   threadIdx.x, threadIdx.y);
}

// ---------------- HMMA GEMM: 128x128 tile, BK=32, 3-stage smem pipeline ----
// smem swizzle: 16B granule g of row r stored at granule (g ^ ((r>>1)&3))
// PHASE 1: H = relu( gather(x16) @ W1t^T )  (K=1024)
// PHASE 2: out[tok] = gate * ( H @ W2t^T )  (K=4096)
template <int PHASE>
__global__ void __launch_bounds__(NTHREADS, 2)
moe_mma_gemm(float* __restrict__ out) {
    constexpr int KA = (PHASE == 1) ? D_DIM : F_DIM;
    constexpr int NC = KA / 32;                 // 32 / 128 k-tiles
    constexpr int NT = (PHASE == 1) ? F_DIM : D_DIM;

    __shared__ uint4 dsm[3072];                 // 48 KB: 3 stages x (A 8KB + B 8KB)
    const uint32_t sbase = smem_u32(dsm);

    const int tid = threadIdx.x;
    const int e = blockIdx.z, m0 = blockIdx.y * BM, n0 = blockIdx.x * BN;

    // ---- load mapping: rbase = tid>>2 (0..31), rows rbase+32i; granule cix = tid&3
    const int rbase = tid >> 2;
    const int cix   = tid & 3;
    const uint32_t dst0 = (uint32_t)rbase * ROWB + (uint32_t)((cix ^ ((rbase >> 1) & 3)) << 4);

    const char* pA[4];
    const char* pB[4];
    uint32_t    mskA = 0;
#pragma unroll
    for (int i = 0; i < 4; i++) {
        int row = rbase + i * 32;
        if (PHASE == 1) {
            int tok = g_tok_of_slot[e * CAP + m0 + row];
            if (tok >= 0) { pA[i] = (const char*)(g_x16 + (size_t)tok * D_DIM) + cix * 16; mskA |= (1u << i); }
            else          { pA[i] = (const char*)g_zrow; }
        } else {
            pA[i] = (const char*)(g_h16 + (size_t)(e * CAP + m0 + row) * F_DIM) + cix * 16;
            mskA |= (1u << i);
        }
        pB[i] = (const char*)(g_wt + ((size_t)e * NT + n0 + row) * KA) + cix * 16;
    }

    uint4 rA[4], rB[4];
    auto ldg_tile = [&](int c) {
        uint32_t koff = (uint32_t)c * ROWB;
#pragma unroll
        for (int i = 0; i < 4; i++) {
            rA[i] = *(const uint4*)(pA[i] + (((mskA >> i) & 1) ? koff : 0u));
            rB[i] = *(const uint4*)(pB[i] + koff);
        }
    };
    auto sts_tile = [&](int buf) {
        uint32_t aS = sbase + (uint32_t)buf * STAGE_B;
        uint32_t bS = aS + 8192;
#pragma unroll
        for (int i = 0; i < 4; i++) {
            sts128(aS + dst0 + i * 2048, rA[i]);
            sts128(bS + dst0 + i * 2048, rB[i]);
        }
    };

    // ---- compute mapping: 4 warps 2x2, warp tile 64x64
    const int w = tid >> 5, l = tid & 31;
    const int warp_m = (w & 1) * 64, warp_n = (w >> 1) * 64;
    const int a_ml = warp_m + (l & 15);
    const int a_ks = (l >> 4);
    const int b_nl = warp_n + (l & 7) + ((l & 16) >> 1);
    const int b_ks = (l >> 3) & 1;
    const int fa = (a_ml >> 1) & 3, fb = (b_nl >> 1) & 3;

    float acc[4][8][4];
#pragma unroll
    for (int i = 0; i < 4; i++)
#pragma unroll
        for (int j = 0; j < 8; j++)
#pragma unroll
            for (int q = 0; q < 4; q++) acc[i][j][q] = 0.f;

    // ---- 3-stage pipeline prologue: buf0 <- tile0, regs <- tile1
    ldg_tile(0);
    sts_tile(0);
    ldg_tile(1);

    int bufc = 0, bufs = 1;
#pragma unroll 2
    for (int c = 0; c < NC; c++) {
        if (c + 1 < NC) sts_tile(bufs);          // store tile c+1 (regs) early
        if (c + 2 < NC) ldg_tile(c + 2);         // 2-tile latency budget
        __syncthreads();

        uint32_t aS = sbase + (uint32_t)bufc * STAGE_B;
        uint32_t bS = aS + 8192;
#pragma unroll
        for (int ks = 0; ks < 2; ks++) {
            uint32_t af[4][4], bf[4][4];
#pragma unroll
            for (int mf = 0; mf < 4; mf++) {
                uint32_t addr = aS + (uint32_t)(a_ml + mf * 16) * ROWB
                              + (uint32_t)(((ks * 2 + a_ks) ^ fa) << 4);
                ldsm4(af[mf][0], af[mf][1], af[mf][2], af[mf][3], addr);
            }
#pragma unroll
            for (int g = 0; g < 4; g++) {
                uint32_t addr = bS + (uint32_t)(b_nl + g * 16) * ROWB
                              + (uint32_t)(((ks * 2 + b_ks) ^ fb) << 4);
                ldsm4(bf[g][0], bf[g][1], bf[g][2], bf[g][3], addr);
            }
#pragma unroll
            for (int mf = 0; mf < 4; mf++)
#pragma unroll
                for (int nf = 0; nf < 8; nf++)
                    mma16816(acc[mf][nf], af[mf], &bf[nf >> 1][(nf & 1) * 2]);
        }
        bufc = (bufc == 2) ? 0 : bufc + 1;
        bufs = (bufs == 2) ? 0 : bufs + 1;
    }

    // ---- epilogue ----
    const int gid = l >> 2, tg = l & 3;
    if (PHASE == 1) {
#pragma unroll
        for (int mf = 0; mf < 4; mf++) {
#pragma unroll
            for (int half = 0; half < 2; half++) {
                int row = warp_m + mf * 16 + gid + half * 8;
                int slot = e * CAP + m0 + row;
                __half* hrow = g_h16 + (size_t)slot * F_DIM;
#pragma unroll
                for (int nf = 0; nf < 8; nf++) {
                    int col = n0 + warp_n + nf * 8 + tg * 2;
                    float v0 = fmaxf(acc[mf][nf][half * 2 + 0], 0.f);
                    float v1 = fmaxf(acc[mf][nf][half * 2 + 1], 0.f);
                    *(__half2*)(hrow + col) = __halves2half2(__float2half_rn(v0), __float2half_rn(v1));
                }
            }
        }
    } else {
#pragma unroll
        for (int mf = 0; mf < 4; mf++) {
#pragma unroll
            for (int half = 0; half < 2; half++) {
                int row = warp_m + mf * 16 + gid + half * 8;
                int slot = e * CAP + m0 + row;
                int tok = g_tok_of_slot[slot];
                if (tok < 0) continue;
                float g = g_slot_gate[slot];
                float* orow = out + (size_t)tok * D_DIM;
#pragma unroll
                for (int nf = 0; nf < 8; nf++) {
                    int col = n0 + warp_n + nf * 8 + tg * 2;
                    float2 v;
                    v.x = acc[mf][nf][half * 2 + 0] * g;
                    v.y = acc[mf][nf][half * 2 + 1] * g;
                    *(float2*)(orow + col) = v;
                }
            }
        }
    }
}

// ---------------- launch ----------------
extern "C" void kernel_launch(void* const* d_in, const int* in_sizes, int n_in,
                              void* d_out, int out_size) {
    const float* x  = (const float*)d_in[0];
    const float* Wr = (const float*)d_in[1];
    const float* W1 = (const float*)d_in[2];
    const float* W2 = (const float*)d_in[3];
    float* out = (float*)d_out;

    // launch 0: router (+x16 conversion, +chunk histogram via atomics)
    router_kernel<<<T_TOK / 8, 256>>>(x, Wr);
    // launch 1: fused reset | scan(+count re-zero) | convert W1
    fused_setup_kernel<<<65 + 32 * 128 * 8, 256>>>(W1);
    // launch 2: slot assignment
    assign_kernel<<<NCHUNK, CHUNK>>>();
    // launch 3: GEMM1  (ncu profiles launch index 3)
    moe_mma_gemm<1><<<dim3(F_DIM / BN, CAP / BM, E_NUM), NTHREADS>>>(nullptr);

    // W2^T overwrites union buffer (stream-ordered after GEMM1), then GEMM2
    convert_w2_kernel<<<dim3(F_DIM / 32, D_DIM / 32, E_NUM), dim3(32, 8)>>>(W2);

    cudaMemsetAsync(d_out, 0, (size_t)out_size * sizeof(float));

    moe_mma_gemm<2><<<dim3(D_DIM / BN, CAP / BM, E_NUM), NTHREADS>>>(out);
}